// round 1
// baseline (speedup 1.0000x reference)
#include <cuda_runtime.h>
#include <mma.h>
#include <math.h>

using namespace nvcuda;

// Problem dims
#define TT 65536
#define DD 256

// GEMM tiling
constexpr int BM = 64;
constexpr int BN = 64;
constexpr int BK = 8;

// Scan chunking
constexpr int CCH = 128;          // timesteps per chunk
constexpr int CC  = TT / CCH;     // 512 chunks

// ---------------- device scratch (no allocations allowed) ----------------
__device__ float g_q0[(size_t)TT * DD];
__device__ float g_q1[(size_t)TT * DD];
__device__ float g_a [(size_t)TT * DD];
__device__ float g_b [(size_t)TT * DD];
__device__ float g_cA[CC * DD];
__device__ float g_cB[CC * DD];
__device__ float g_hp[CC * DD];

// ---------------- init: broadcast question into q0 ----------------
__global__ void __launch_bounds__(256) init_q_kernel(float* __restrict__ q0,
                                                     const float* __restrict__ question) {
    size_t i = (size_t)blockIdx.x * blockDim.x + threadIdx.x;
    if (i < (size_t)TT * DD) q0[i] = question[i & (DD - 1)];
}

// ---------------- tf32 helpers ----------------
template <class Frag>
__device__ __forceinline__ void frag_to_tf32(Frag& f) {
#pragma unroll
    for (int i = 0; i < f.num_elements; i++) f.x[i] = wmma::__float_to_tf32(f.x[i]);
}

// ---------------- fused GEMM: produces a,b for one direction ----------------
// zpre = (x*q) @ Wz + bz ; hpre = x @ Wh[0:D] + q @ Wh[D:2D] + bh
// a = 1 - sigmoid(zpre); b = sigmoid(zpre) * tanh(hpre)
// REVERSE: store output rows at (T-1-t) so the scan always runs forward in memory.
template <bool REVERSE>
__global__ void __launch_bounds__(128) gemm_ab_kernel(
    const float* __restrict__ x, const float* __restrict__ q,
    const float* __restrict__ Wz, const float* __restrict__ bz,
    const float* __restrict__ Wh, const float* __restrict__ bh,
    float* __restrict__ ga, float* __restrict__ gb)
{
    __shared__ float xs[BM][16];
    __shared__ float qs[BM][16];
    __shared__ float us[BM][16];
    __shared__ float zs[BM][BN];
    __shared__ float hs[BM][BN];

    const int t0  = blockIdx.x * BM;
    const int n0  = blockIdx.y * BN;
    const int tid = threadIdx.x;
    const int warp = tid >> 5;
    const int wm = warp >> 1;   // 0..1 (rows)
    const int wn = warp & 1;    // 0..1 (cols)

    wmma::fragment<wmma::accumulator, 16, 16, 8, float> accz[2][2], acch[2][2];
#pragma unroll
    for (int mi = 0; mi < 2; mi++)
#pragma unroll
        for (int ni = 0; ni < 2; ni++) {
            wmma::fill_fragment(accz[mi][ni], 0.0f);
            wmma::fill_fragment(acch[mi][ni], 0.0f);
        }

    for (int k0 = 0; k0 < DD; k0 += BK) {
        // stage x,q (and compute u = x*q) : 64x8 tiles, 128 threads -> float4 each
        {
            int r  = tid >> 1;
            int c4 = (tid & 1) * 4;
            const float4 xv = *(const float4*)(x + (size_t)(t0 + r) * DD + k0 + c4);
            const float4 qv = *(const float4*)(q + (size_t)(t0 + r) * DD + k0 + c4);
            *(float4*)&xs[r][c4] = xv;
            *(float4*)&qs[r][c4] = qv;
            float4 uv = make_float4(xv.x * qv.x, xv.y * qv.y, xv.z * qv.z, xv.w * qv.w);
            *(float4*)&us[r][c4] = uv;
        }
        __syncthreads();

        // B fragments straight from global (weights are small, L1/L2 resident)
        wmma::fragment<wmma::matrix_b, 16, 16, 8, wmma::precision::tf32, wmma::row_major> bzf[2], bh0[2], bh1[2];
#pragma unroll
        for (int ni = 0; ni < 2; ni++) {
            const int n = n0 + wn * 32 + ni * 16;
            wmma::load_matrix_sync(bzf[ni], Wz + (size_t)k0 * DD + n, DD);
            wmma::load_matrix_sync(bh0[ni], Wh + (size_t)k0 * DD + n, DD);
            wmma::load_matrix_sync(bh1[ni], Wh + (size_t)(DD + k0) * DD + n, DD);
            frag_to_tf32(bzf[ni]);
            frag_to_tf32(bh0[ni]);
            frag_to_tf32(bh1[ni]);
        }

#pragma unroll
        for (int mi = 0; mi < 2; mi++) {
            wmma::fragment<wmma::matrix_a, 16, 16, 8, wmma::precision::tf32, wmma::row_major> au, ax, aq;
            const int r = wm * 32 + mi * 16;
            wmma::load_matrix_sync(au, &us[r][0], 16);
            wmma::load_matrix_sync(ax, &xs[r][0], 16);
            wmma::load_matrix_sync(aq, &qs[r][0], 16);
            frag_to_tf32(au);
            frag_to_tf32(ax);
            frag_to_tf32(aq);
#pragma unroll
            for (int ni = 0; ni < 2; ni++) {
                wmma::mma_sync(accz[mi][ni], au, bzf[ni], accz[mi][ni]);
                wmma::mma_sync(acch[mi][ni], ax, bh0[ni], acch[mi][ni]);
                wmma::mma_sync(acch[mi][ni], aq, bh1[ni], acch[mi][ni]);
            }
        }
        __syncthreads();
    }

    // spill accumulators to smem
#pragma unroll
    for (int mi = 0; mi < 2; mi++)
#pragma unroll
        for (int ni = 0; ni < 2; ni++) {
            wmma::store_matrix_sync(&zs[wm * 32 + mi * 16][wn * 32 + ni * 16], accz[mi][ni], BN, wmma::mem_row_major);
            wmma::store_matrix_sync(&hs[wm * 32 + mi * 16][wn * 32 + ni * 16], acch[mi][ni], BN, wmma::mem_row_major);
        }
    __syncthreads();

    // elementwise epilogue + store a,b (optionally time-reversed rows)
    {
        const int r     = tid >> 1;
        const int cbase = (tid & 1) * 32;
        const int tg    = t0 + r;
        const int row_out = REVERSE ? (TT - 1 - tg) : tg;
        float* pa = ga + (size_t)row_out * DD + n0 + cbase;
        float* pb = gb + (size_t)row_out * DD + n0 + cbase;
#pragma unroll
        for (int c = 0; c < 32; c++) {
            const float zp = zs[r][cbase + c] + bz[n0 + cbase + c];
            const float hp = hs[r][cbase + c] + bh[n0 + cbase + c];
            const float z  = 1.0f / (1.0f + expf(-zp));
            const float ht = tanhf(hp);
            pa[c] = 1.0f - z;
            pb[c] = z * ht;
        }
    }
}

// ---------------- scan pass A: per-chunk composition totals ----------------
__global__ void __launch_bounds__(256) scanA_kernel(const float* __restrict__ ga,
                                                    const float* __restrict__ gb,
                                                    float* __restrict__ cA,
                                                    float* __restrict__ cB)
{
    const int c = blockIdx.x;
    const int j = threadIdx.x;
    const float* pa = ga + (size_t)c * CCH * DD + j;
    const float* pb = gb + (size_t)c * CCH * DD + j;
    float A = 1.0f, B = 0.0f;
#pragma unroll 8
    for (int t = 0; t < CCH; t++) {
        const float a = pa[(size_t)t * DD];
        const float b = pb[(size_t)t * DD];
        B = fmaf(a, B, b);
        A = A * a;
    }
    cA[c * DD + j] = A;
    cB[c * DD + j] = B;
}

// ---------------- scan pass B: cross-chunk sequential, exclusive prefix h ----------------
__global__ void __launch_bounds__(256) scanB_kernel(const float* __restrict__ cA,
                                                    const float* __restrict__ cB,
                                                    float* __restrict__ hp,
                                                    float* __restrict__ out)
{
    const int j = threadIdx.x;
    float h = 0.0f;
#pragma unroll 8
    for (int c = 0; c < CC; c++) {
        hp[c * DD + j] = h;
        h = fmaf(cA[c * DD + j], h, cB[c * DD + j]);
    }
    if (out) out[j] = h;   // final state (used for last layer forward = kernel output)
}

// ---------------- scan pass C: apply prefix, write h into q_next ----------------
// MODE 0: q_next[t] = h   (forward direction)
// MODE 1: q_next[T-1-t] += h  (backward direction, realign to forward order)
template <int MODE>
__global__ void __launch_bounds__(256) scanC_kernel(const float* __restrict__ ga,
                                                    const float* __restrict__ gb,
                                                    const float* __restrict__ hp,
                                                    float* __restrict__ qn)
{
    const int c = blockIdx.x;
    const int j = threadIdx.x;
    float h = hp[c * DD + j];
    const float* pa = ga + (size_t)c * CCH * DD + j;
    const float* pb = gb + (size_t)c * CCH * DD + j;
#pragma unroll 4
    for (int t = 0; t < CCH; t++) {
        h = fmaf(pa[(size_t)t * DD], h, pb[(size_t)t * DD]);
        const int tg = c * CCH + t;
        if (MODE == 0) {
            qn[(size_t)tg * DD + j] = h;
        } else {
            qn[(size_t)(TT - 1 - tg) * DD + j] += h;
        }
    }
}

// ---------------- host orchestration ----------------
static void run_direction(const float* story, const float* q,
                          const float* Wz, const float* bz,
                          const float* Wh, const float* bh,
                          bool reverse,
                          float* pa, float* pb, float* pcA, float* pcB, float* php,
                          float* q_next,   // nullptr for last layer
                          float* out)      // nullptr except last layer fwd
{
    dim3 ggrid(TT / BM, DD / BN);
    if (reverse)
        gemm_ab_kernel<true><<<ggrid, 128>>>(story, q, Wz, bz, Wh, bh, pa, pb);
    else
        gemm_ab_kernel<false><<<ggrid, 128>>>(story, q, Wz, bz, Wh, bh, pa, pb);

    scanA_kernel<<<CC, 256>>>(pa, pb, pcA, pcB);
    scanB_kernel<<<1, 256>>>(pcA, pcB, php, out);

    if (q_next) {
        if (reverse)
            scanC_kernel<1><<<CC, 256>>>(pa, pb, php, q_next);
        else
            scanC_kernel<0><<<CC, 256>>>(pa, pb, php, q_next);
    }
}

extern "C" void kernel_launch(void* const* d_in, const int* in_sizes, int n_in,
                              void* d_out, int out_size)
{
    const float* story    = (const float*)d_in[0];
    const float* question = (const float*)d_in[1];
    const float* Wz_f = (const float*)d_in[2];
    const float* bz_f = (const float*)d_in[3];
    const float* Wh_f = (const float*)d_in[4];
    const float* bh_f = (const float*)d_in[5];
    const float* Wz_b = (const float*)d_in[6];
    const float* bz_b = (const float*)d_in[7];
    const float* Wh_b = (const float*)d_in[8];
    const float* bh_b = (const float*)d_in[9];
    float* out = (float*)d_out;

    float *pq0, *pq1, *pa, *pb, *pcA, *pcB, *php;
    cudaGetSymbolAddress((void**)&pq0, g_q0);
    cudaGetSymbolAddress((void**)&pq1, g_q1);
    cudaGetSymbolAddress((void**)&pa,  g_a);
    cudaGetSymbolAddress((void**)&pb,  g_b);
    cudaGetSymbolAddress((void**)&pcA, g_cA);
    cudaGetSymbolAddress((void**)&pcB, g_cB);
    cudaGetSymbolAddress((void**)&php, g_hp);

    // layer-0 question broadcast
    init_q_kernel<<<(TT * DD) / 256, 256>>>(pq0, question);

    const size_t WZ_L = (size_t)DD * DD;      // 65536
    const size_t WH_L = (size_t)2 * DD * DD;  // 131072

    float* qcur = pq0;
    float* qnxt = pq1;

    for (int layer = 0; layer < 3; layer++) {
        const float* wzf = Wz_f + layer * WZ_L;
        const float* bzf = bz_f + layer * DD;
        const float* whf = Wh_f + layer * WH_L;
        const float* bhf = bh_f + layer * DD;

        if (layer < 2) {
            const float* wzb = Wz_b + layer * WZ_L;
            const float* bzb = bz_b + layer * DD;
            const float* whb = Wh_b + layer * WH_L;
            const float* bhb = bh_b + layer * DD;

            // forward: q_next = h_fwd
            run_direction(story, qcur, wzf, bzf, whf, bhf, false,
                          pa, pb, pcA, pcB, php, qnxt, nullptr);
            // backward: q_next += h_bwd (realigned)
            run_direction(story, qcur, wzb, bzb, whb, bhb, true,
                          pa, pb, pcA, pcB, php, qnxt, nullptr);

            float* t = qcur; qcur = qnxt; qnxt = t;
        } else {
            // last layer: forward only; output = final scan state
            run_direction(story, qcur, wzf, bzf, whf, bhf, false,
                          pa, pb, pcA, pcB, php, nullptr, out);
        }
    }
}

// round 2
// speedup vs baseline: 1.5043x; 1.5043x over previous
#include <cuda_runtime.h>
#include <mma.h>
#include <math.h>

using namespace nvcuda;

#define TT 65536
#define DD 256

constexpr int BM = 128;
constexpr int BN = 64;
constexpr int BK = 16;
constexpr int NKIT = DD / BK;      // 16
constexpr int CCH = BM;            // chunk == BM rows
constexpr int CC  = TT / CCH;      // 512
constexpr int APITCH = 20;         // padded A-tile pitch
constexpr int WPITCH = 68;         // padded W-tile pitch

// ---------------- device scratch ----------------
__device__ float g_q0[(size_t)TT * DD];
__device__ float g_q1[(size_t)TT * DD];
__device__ float g_af[(size_t)TT * DD];
__device__ float g_bf[(size_t)TT * DD];
__device__ float g_ab2[(size_t)TT * DD];
__device__ float g_bb2[(size_t)TT * DD];
__device__ float g_cA[2][CC * DD];
__device__ float g_cB[2][CC * DD];
__device__ float g_hp[2][CC * DD];

typedef wmma::fragment<wmma::accumulator, 16, 16, 8, float> AccFrag;
typedef wmma::fragment<wmma::matrix_a, 16, 16, 8, wmma::precision::tf32, wmma::row_major> AFrag;
typedef wmma::fragment<wmma::matrix_b, 16, 16, 8, wmma::precision::tf32, wmma::row_major> BFrag;

template <class F>
__device__ __forceinline__ void to_tf32(F& f) {
#pragma unroll
    for (int i = 0; i < f.num_elements; i++) f.x[i] = wmma::__float_to_tf32(f.x[i]);
}

// ---------------- fused epilogue: activation + a,b store + chunk-scan totals ----------------
template <bool WRITE_AB>
__device__ __forceinline__ void epilogue_dir(
    float* sm, AccFrag* zacc, AccFrag* hacc,
    const float* __restrict__ bz, const float* __restrict__ bh,
    float* __restrict__ ga, float* __restrict__ gb,
    float* __restrict__ cA, float* __restrict__ cB,
    bool rev, int t0, int n0, int cblk, int tid, int wm, int wn)
{
    float* ez = sm;
    float* eh = sm + BM * WPITCH;
    float* pA = sm + 2 * BM * WPITCH;
    float* pB = pA + 8 * 64;

    __syncthreads();
#pragma unroll
    for (int ni = 0; ni < 2; ni++) {
        wmma::store_matrix_sync(ez + (wm * 16) * WPITCH + wn * 32 + ni * 16, zacc[ni], WPITCH, wmma::mem_row_major);
        wmma::store_matrix_sync(eh + (wm * 16) * WPITCH + wn * 32 + ni * 16, hacc[ni], WPITCH, wmma::mem_row_major);
    }
    __syncthreads();

    {
        const int r  = tid >> 2;
        const int cg = (tid & 3) * 16;
        float av[16], bv[16];
#pragma unroll
        for (int c = 0; c < 16; c++) {
            const int col = cg + c;
            const float zp = ez[r * WPITCH + col] + __ldg(bz + n0 + col);
            const float hh = eh[r * WPITCH + col] + __ldg(bh + n0 + col);
            const float z  = 1.0f / (1.0f + __expf(-zp));
            const float th = tanhf(hh);
            av[c] = 1.0f - z;
            bv[c] = z * th;
        }
#pragma unroll
        for (int c = 0; c < 16; c++) {
            ez[r * WPITCH + cg + c] = av[c];
            eh[r * WPITCH + cg + c] = bv[c];
        }
        if (WRITE_AB) {
            const int tg = t0 + r;
            const size_t ro = rev ? (size_t)(TT - 1 - tg) : (size_t)tg;
#pragma unroll
            for (int i = 0; i < 4; i++) {
                *(float4*)(ga + ro * DD + n0 + cg + i * 4) =
                    make_float4(av[i * 4], av[i * 4 + 1], av[i * 4 + 2], av[i * 4 + 3]);
                *(float4*)(gb + ro * DD + n0 + cg + i * 4) =
                    make_float4(bv[i * 4], bv[i * 4 + 1], bv[i * 4 + 2], bv[i * 4 + 3]);
            }
        }
    }
    __syncthreads();

    // chunk-scan partial composition: 8 segments of 16 rows per channel
    {
        const int ch  = tid & 63;
        const int seg = tid >> 6;
        float A = 1.0f, B = 0.0f;
#pragma unroll
        for (int i = 0; i < 16; i++) {
            const int p   = seg * 16 + i;
            const int row = rev ? (127 - p) : p;
            const float a = ez[row * WPITCH + ch];
            const float b = eh[row * WPITCH + ch];
            B = fmaf(a, B, b);
            A *= a;
        }
        pA[seg * 64 + ch] = A;
        pB[seg * 64 + ch] = B;
    }
    __syncthreads();
    if (tid < 64) {
        float A = 1.0f, B = 0.0f;
#pragma unroll
        for (int s = 0; s < 8; s++) {
            const float a = pA[s * 64 + tid];
            const float b = pB[s * 64 + tid];
            B = fmaf(a, B, b);
            A *= a;
        }
        const int ci = rev ? (CC - 1 - cblk) : cblk;
        cA[ci * DD + n0 + tid] = A;
        cB[ci * DD + n0 + tid] = B;
    }
    __syncthreads();
}

// ---------------- fused dual-direction GEMM ----------------
// fwd: z/h from (u,x,q) @ (Wzf, Whf[0:D], Whf[D:2D]); bwd same with _b weights,
// a,b stored time-reversed. QB: q is a broadcast D-vector (layer 0 question).
template <bool DUAL, bool WRITE_AB, bool QB>
__global__ void __launch_bounds__(512, 1) gemm_fused_kernel(
    const float* __restrict__ x, const float* __restrict__ q,
    const float* __restrict__ Wzf, const float* __restrict__ bzf,
    const float* __restrict__ Whf, const float* __restrict__ bhf,
    const float* __restrict__ Wzb, const float* __restrict__ bzb,
    const float* __restrict__ Whb, const float* __restrict__ bhb,
    float* __restrict__ gaf, float* __restrict__ gbf,
    float* __restrict__ cAf, float* __restrict__ cBf,
    float* __restrict__ gab, float* __restrict__ gbb,
    float* __restrict__ cAb, float* __restrict__ cBb)
{
    constexpr int WT = DUAL ? 6 : 3;
    extern __shared__ float sm[];
    float* sx = sm;                       // [2][BM][APITCH]
    float* sq = sx + 2 * BM * APITCH;
    float* su = sq + 2 * BM * APITCH;
    float* sw = su + 2 * BM * APITCH;     // [2][WT][16][WPITCH]

    const int tid  = threadIdx.x;
    const int warp = tid >> 5;
    const int wm   = warp >> 1;           // 0..7
    const int wn   = warp & 1;            // 0..1
    const int cblk = blockIdx.y;
    const int t0   = cblk * BM;
    const int n0   = blockIdx.x * BN;

    AccFrag zf[2], hf[2], zb[2], hb[2];
#pragma unroll
    for (int ni = 0; ni < 2; ni++) {
        wmma::fill_fragment(zf[ni], 0.0f);
        wmma::fill_fragment(hf[ni], 0.0f);
        if (DUAL) {
            wmma::fill_fragment(zb[ni], 0.0f);
            wmma::fill_fragment(hb[ni], 0.0f);
        }
    }

    const int lr = tid >> 2;
    const int lc = (tid & 3) * 4;

    auto loadA = [&](int k0, float4& rx, float4& rq) {
        rx = *(const float4*)(x + (size_t)(t0 + lr) * DD + k0 + lc);
        if (QB) rq = *(const float4*)(q + k0 + lc);
        else    rq = *(const float4*)(q + (size_t)(t0 + lr) * DD + k0 + lc);
    };
    auto storeA = [&](int buf, float4 rx, float4 rq) {
        *(float4*)(sx + buf * BM * APITCH + lr * APITCH + lc) = rx;
        *(float4*)(sq + buf * BM * APITCH + lr * APITCH + lc) = rq;
        float4 ru = make_float4(rx.x * rq.x, rx.y * rq.y, rx.z * rq.z, rx.w * rq.w);
        *(float4*)(su + buf * BM * APITCH + lr * APITCH + lc) = ru;
    };
    auto wsrc = [&](int tile, int row, int col) -> const float* {
        switch (tile) {
            case 0:  return Wzf + (size_t)row * DD + col;
            case 1:  return Whf + (size_t)row * DD + col;
            case 2:  return Whf + (size_t)(DD + row) * DD + col;
            case 3:  return Wzb + (size_t)row * DD + col;
            case 4:  return Whb + (size_t)row * DD + col;
            default: return Whb + (size_t)(DD + row) * DD + col;
        }
    };
    auto loadW = [&](int k0, float4* rw) {
#pragma unroll
        for (int p = 0; p < 3; p++) {
            const int idx = p * 512 + tid;
            if (idx < WT * 256) {
                const int tile = idx >> 8, wi = idx & 255;
                const int row = wi >> 4, col4 = (wi & 15) * 4;
                rw[p] = *(const float4*)wsrc(tile, k0 + row, n0 + col4);
            }
        }
    };
    auto storeW = [&](int buf, const float4* rw) {
#pragma unroll
        for (int p = 0; p < 3; p++) {
            const int idx = p * 512 + tid;
            if (idx < WT * 256) {
                const int tile = idx >> 8, wi = idx & 255;
                const int row = wi >> 4, col4 = (wi & 15) * 4;
                *(float4*)(sw + buf * WT * 16 * WPITCH + tile * 16 * WPITCH + row * WPITCH + col4) = rw[p];
            }
        }
    };

    {
        float4 rx, rq, rw[3];
        loadA(0, rx, rq);
        loadW(0, rw);
        storeA(0, rx, rq);
        storeW(0, rw);
    }
    __syncthreads();

    int buf = 0;
    for (int it = 0; it < NKIT; ++it) {
        float4 rx, rq, rw[3];
        const bool pre = (it + 1 < NKIT);
        if (pre) {
            loadA((it + 1) * BK, rx, rq);
            loadW((it + 1) * BK, rw);
        }
#pragma unroll
        for (int kk = 0; kk < 2; kk++) {
            AFrag au, ax, aq;
            wmma::load_matrix_sync(ax, sx + buf * BM * APITCH + (wm * 16) * APITCH + kk * 8, APITCH);
            wmma::load_matrix_sync(aq, sq + buf * BM * APITCH + (wm * 16) * APITCH + kk * 8, APITCH);
            wmma::load_matrix_sync(au, su + buf * BM * APITCH + (wm * 16) * APITCH + kk * 8, APITCH);
            to_tf32(ax); to_tf32(aq); to_tf32(au);
            const float* wb = sw + buf * WT * 16 * WPITCH + (kk * 8) * WPITCH + wn * 32;
#pragma unroll
            for (int ni = 0; ni < 2; ni++) {
                BFrag b0, b1, b2;
                wmma::load_matrix_sync(b0, wb + 0 * 16 * WPITCH + ni * 16, WPITCH);
                wmma::load_matrix_sync(b1, wb + 1 * 16 * WPITCH + ni * 16, WPITCH);
                wmma::load_matrix_sync(b2, wb + 2 * 16 * WPITCH + ni * 16, WPITCH);
                to_tf32(b0); to_tf32(b1); to_tf32(b2);
                wmma::mma_sync(zf[ni], au, b0, zf[ni]);
                wmma::mma_sync(hf[ni], ax, b1, hf[ni]);
                wmma::mma_sync(hf[ni], aq, b2, hf[ni]);
                if constexpr (DUAL) {
                    BFrag b3, b4, b5;
                    wmma::load_matrix_sync(b3, wb + 3 * 16 * WPITCH + ni * 16, WPITCH);
                    wmma::load_matrix_sync(b4, wb + 4 * 16 * WPITCH + ni * 16, WPITCH);
                    wmma::load_matrix_sync(b5, wb + 5 * 16 * WPITCH + ni * 16, WPITCH);
                    to_tf32(b3); to_tf32(b4); to_tf32(b5);
                    wmma::mma_sync(zb[ni], au, b3, zb[ni]);
                    wmma::mma_sync(hb[ni], ax, b4, hb[ni]);
                    wmma::mma_sync(hb[ni], aq, b5, hb[ni]);
                }
            }
        }
        if (pre) {
            storeA(buf ^ 1, rx, rq);
            storeW(buf ^ 1, rw);
        }
        __syncthreads();
        buf ^= 1;
    }

    epilogue_dir<WRITE_AB>(sm, zf, hf, bzf, bhf, gaf, gbf, cAf, cBf, false, t0, n0, cblk, tid, wm, wn);
    if constexpr (DUAL) {
        epilogue_dir<WRITE_AB>(sm, zb, hb, bzb, bhb, gab, gbb, cAb, cBb, true, t0, n0, cblk, tid, wm, wn);
    }
}

// ---------------- scanB: cross-chunk sequential with register prefetch ----------------
// grid up to 2 blocks: block 0 -> set0 (writes out if non-null), block 1 -> set1.
__global__ void __launch_bounds__(DD) scanB_kernel(
    const float* __restrict__ cA0, const float* __restrict__ cB0, float* __restrict__ hp0,
    const float* __restrict__ cA1, const float* __restrict__ cB1, float* __restrict__ hp1,
    float* __restrict__ out)
{
    const float* cA = blockIdx.x ? cA1 : cA0;
    const float* cB = blockIdx.x ? cB1 : cB0;
    float* hp = blockIdx.x ? hp1 : hp0;
    const int j = threadIdx.x;
    constexpr int G = 16;
    constexpr int NG = CC / G;  // 32

    float A0[G], B0[G], A1[G], B1[G];
#pragma unroll
    for (int i = 0; i < G; i++) {
        A0[i] = __ldg(cA + i * DD + j);
        B0[i] = __ldg(cB + i * DD + j);
    }
    float h = 0.0f;
    for (int g = 0; g < NG; g += 2) {
        if (g + 1 < NG) {
#pragma unroll
            for (int i = 0; i < G; i++) {
                A1[i] = __ldg(cA + ((g + 1) * G + i) * DD + j);
                B1[i] = __ldg(cB + ((g + 1) * G + i) * DD + j);
            }
        }
#pragma unroll
        for (int i = 0; i < G; i++) {
            hp[(g * G + i) * DD + j] = h;
            h = fmaf(A0[i], h, B0[i]);
        }
        if (g + 2 < NG) {
#pragma unroll
            for (int i = 0; i < G; i++) {
                A0[i] = __ldg(cA + ((g + 2) * G + i) * DD + j);
                B0[i] = __ldg(cB + ((g + 2) * G + i) * DD + j);
            }
        }
        if (g + 1 < NG) {
#pragma unroll
            for (int i = 0; i < G; i++) {
                hp[((g + 1) * G + i) * DD + j] = h;
                h = fmaf(A1[i], h, B1[i]);
            }
        }
    }
    if (out && blockIdx.x == 0) out[j] = h;
}

// ---------------- scanC: apply prefix, write h into q_next ----------------
template <int MODE>
__global__ void __launch_bounds__(DD) scanC_kernel(const float* __restrict__ ga,
                                                   const float* __restrict__ gb,
                                                   const float* __restrict__ hp,
                                                   float* __restrict__ qn)
{
    const int c = blockIdx.x;
    const int j = threadIdx.x;
    float h = hp[c * DD + j];
    const float* pa = ga + (size_t)c * CCH * DD + j;
    const float* pb = gb + (size_t)c * CCH * DD + j;
#pragma unroll 8
    for (int t = 0; t < CCH; t++) {
        h = fmaf(pa[(size_t)t * DD], h, pb[(size_t)t * DD]);
        const int tg = c * CCH + t;
        if (MODE == 0) {
            qn[(size_t)tg * DD + j] = h;
        } else {
            qn[(size_t)(TT - 1 - tg) * DD + j] += h;
        }
    }
}

// ---------------- host orchestration ----------------
extern "C" void kernel_launch(void* const* d_in, const int* in_sizes, int n_in,
                              void* d_out, int out_size)
{
    const float* story    = (const float*)d_in[0];
    const float* question = (const float*)d_in[1];
    const float* Wz_f = (const float*)d_in[2];
    const float* bz_f = (const float*)d_in[3];
    const float* Wh_f = (const float*)d_in[4];
    const float* bh_f = (const float*)d_in[5];
    const float* Wz_b = (const float*)d_in[6];
    const float* bz_b = (const float*)d_in[7];
    const float* Wh_b = (const float*)d_in[8];
    const float* bh_b = (const float*)d_in[9];
    float* out = (float*)d_out;

    float *pq0, *pq1, *paf, *pbf, *pab, *pbb, *pcA, *pcB, *php;
    cudaGetSymbolAddress((void**)&pq0, g_q0);
    cudaGetSymbolAddress((void**)&pq1, g_q1);
    cudaGetSymbolAddress((void**)&paf, g_af);
    cudaGetSymbolAddress((void**)&pbf, g_bf);
    cudaGetSymbolAddress((void**)&pab, g_ab2);
    cudaGetSymbolAddress((void**)&pbb, g_bb2);
    cudaGetSymbolAddress((void**)&pcA, g_cA);
    cudaGetSymbolAddress((void**)&pcB, g_cB);
    cudaGetSymbolAddress((void**)&php, g_hp);
    float* pcA0 = pcA;            float* pcA1 = pcA + CC * DD;
    float* pcB0 = pcB;            float* pcB1 = pcB + CC * DD;
    float* php0 = php;            float* php1 = php + CC * DD;

    const int SMEM_DUAL   = (6 * BM * APITCH + 2 * 6 * 16 * WPITCH) * 4;  // 113664
    const int SMEM_SINGLE = (6 * BM * APITCH + 2 * 3 * 16 * WPITCH) * 4;  // 87552

    cudaFuncSetAttribute(gemm_fused_kernel<true, true, true>,
                         cudaFuncAttributeMaxDynamicSharedMemorySize, SMEM_DUAL);
    cudaFuncSetAttribute(gemm_fused_kernel<true, true, false>,
                         cudaFuncAttributeMaxDynamicSharedMemorySize, SMEM_DUAL);
    cudaFuncSetAttribute(gemm_fused_kernel<false, false, false>,
                         cudaFuncAttributeMaxDynamicSharedMemorySize, SMEM_SINGLE);

    const size_t WZ_L = (size_t)DD * DD;
    const size_t WH_L = (size_t)2 * DD * DD;
    const dim3 grid(DD / BN, TT / BM);  // (4, 512): n-quarter fastest for x/q L2 reuse

    // ---- layer 0 (q = broadcast question) ----
    gemm_fused_kernel<true, true, true><<<grid, 512, SMEM_DUAL>>>(
        story, question,
        Wz_f, bz_f, Wh_f, bh_f, Wz_b, bz_b, Wh_b, bh_b,
        paf, pbf, pcA0, pcB0, pab, pbb, pcA1, pcB1);
    scanB_kernel<<<2, DD>>>(pcA0, pcB0, php0, pcA1, pcB1, php1, nullptr);
    scanC_kernel<0><<<CC, DD>>>(paf, pbf, php0, pq0);
    scanC_kernel<1><<<CC, DD>>>(pab, pbb, php1, pq0);

    // ---- layer 1 ----
    gemm_fused_kernel<true, true, false><<<grid, 512, SMEM_DUAL>>>(
        story, pq0,
        Wz_f + WZ_L, bz_f + DD, Wh_f + WH_L, bh_f + DD,
        Wz_b + WZ_L, bz_b + DD, Wh_b + WH_L, bh_b + DD,
        paf, pbf, pcA0, pcB0, pab, pbb, pcA1, pcB1);
    scanB_kernel<<<2, DD>>>(pcA0, pcB0, php0, pcA1, pcB1, php1, nullptr);
    scanC_kernel<0><<<CC, DD>>>(paf, pbf, php0, pq1);
    scanC_kernel<1><<<CC, DD>>>(pab, pbb, php1, pq1);

    // ---- layer 2 (forward only; final state is the output) ----
    gemm_fused_kernel<false, false, false><<<grid, 512, SMEM_SINGLE>>>(
        story, pq1,
        Wz_f + 2 * WZ_L, bz_f + 2 * DD, Wh_f + 2 * WH_L, bh_f + 2 * DD,
        nullptr, nullptr, nullptr, nullptr,
        paf, pbf, pcA0, pcB0, nullptr, nullptr, nullptr, nullptr);
    scanB_kernel<<<1, DD>>>(pcA0, pcB0, php0, pcA0, pcB0, php0, out);
}